// round 10
// baseline (speedup 1.0000x reference)
#include <cuda_runtime.h>
#include <cuda_bf16.h>
#include <cstdint>

#define NROWS 262144
#define DD 128
#define HH 16
#define EE 21

#define THREADS 512                // 16 warps, 4 per SMSP
#define M_TILE 128                 // rows per slab (16 warps x 8 rows)
#define GRID_MAIN 148

#define XSLAB_BYTES (M_TILE * DD * 4)         // 65536
#define SMEM_BYTES (3 * XSLAB_BYTES + 3 * 160 + 3 * M_TILE * 4)   // ~199KB

__device__ int g_counts[EE];
__device__ int g_cursor[EE];
__device__ int g_offsets[EE + 1];
__device__ int g_tileOff[EE + 1];
__device__ int g_numTiles;
__device__ int g_perm[NROWS];
__device__ float g_Wsplit[EE][DD * HH];   // tf32-rounded W1, [d][h] contiguous

// ---------------- K1: histogram (int4 vectorized) ----------------
__global__ void k_hist(const int* __restrict__ sid) {
    __shared__ int sh[EE];
    int tid = threadIdx.x;
    if (tid < EE) sh[tid] = 0;
    __syncthreads();
    int4 v = ((const int4*)sid)[blockIdx.x * blockDim.x + tid];
    atomicAdd(&sh[v.x], 1);
    atomicAdd(&sh[v.y], 1);
    atomicAdd(&sh[v.z], 1);
    atomicAdd(&sh[v.w], 1);
    __syncthreads();
    if (tid < EE) atomicAdd(&g_counts[tid], sh[tid]);
}

// ---------------- K2: block0 = warp scan; blocks 1..21 = tf32 weight prep ----
__global__ void k_scan_prep(const float* __restrict__ W1) {
    if (blockIdx.x == 0) {
        if (threadIdx.x < 32) {
            int t = threadIdx.x;
            int c  = (t < EE) ? g_counts[t] : 0;
            int tl = (c + M_TILE - 1) / M_TILE;
            int ic = c, it = tl;
            #pragma unroll
            for (int d = 1; d < 32; d <<= 1) {
                int vc = __shfl_up_sync(0xFFFFFFFFu, ic, d);
                int vt = __shfl_up_sync(0xFFFFFFFFu, it, d);
                if (t >= d) { ic += vc; it += vt; }
            }
            if (t < EE) {
                g_offsets[t] = ic - c;
                g_cursor[t]  = ic - c;
                g_tileOff[t] = it - tl;
                g_counts[t]  = 0;
            }
            int totC = __shfl_sync(0xFFFFFFFFu, ic, EE - 1);
            int totT = __shfl_sync(0xFFFFFFFFu, it, EE - 1);
            if (t == 0) {
                g_offsets[EE] = totC;
                g_tileOff[EE] = totT;
                g_numTiles = totT;
            }
        }
    } else {
        int e = blockIdx.x - 1;
        for (int i = threadIdx.x; i < DD * HH; i += blockDim.x) {
            float w = W1[e * DD * HH + i];
            uint32_t hb;
            asm("cvt.rna.tf32.f32 %0, %1;" : "=r"(hb) : "f"(w));
            g_Wsplit[e][i] = __uint_as_float(hb);
        }
    }
}

// ---------------- K3: scatter ----------------
__global__ void k_scatter(const int* __restrict__ sid) {
    __shared__ int sHist[EE];
    __shared__ int sBase[EE];
    int tid = threadIdx.x;
    if (tid < EE) sHist[tid] = 0;
    __syncthreads();
    int gid = blockIdx.x * blockDim.x + tid;
    int e = sid[gid];
    int myIdx = atomicAdd(&sHist[e], 1);
    __syncthreads();
    if (tid < EE) sBase[tid] = atomicAdd(&g_cursor[tid], sHist[tid]);
    __syncthreads();
    g_perm[sBase[e] + myIdx] = gid;
}

// ---------------- K4: tf32-MMA, 16 warps, reg-resident W ----------------
__device__ __forceinline__ void cp_async16(uint32_t dst, const void* src) {
    asm volatile("cp.async.cg.shared.global [%0], [%1], 16;\n" :: "r"(dst), "l"(src));
}
__device__ __forceinline__ void cp_async4(uint32_t dst, const void* src) {
    asm volatile("cp.async.ca.shared.global [%0], [%1], 4;\n" :: "r"(dst), "l"(src));
}
#define CP_COMMIT() asm volatile("cp.async.commit_group;" ::: "memory")
#define CP_WAIT2()  asm volatile("cp.async.wait_group 2;" ::: "memory")

#define MMA_TF32(C0,C1,C2,C3, A0,A1,A2,A3, B0,B1)                                  \
    asm volatile("mma.sync.aligned.m16n8k8.row.col.f32.tf32.tf32.f32 "             \
        "{%0,%1,%2,%3}, {%4,%5,%6,%7}, {%8,%9}, {%0,%1,%2,%3};"                    \
        : "+f"(C0), "+f"(C1), "+f"(C2), "+f"(C3)                                   \
        : "r"(A0), "r"(A1), "r"(A2), "r"(A3), "r"(B0), "r"(B1))

__global__ __launch_bounds__(THREADS, 1)
void k_main(const float* __restrict__ x,
            const float* __restrict__ W1,
            const float* __restrict__ b1,
            const float* __restrict__ W2,
            const float* __restrict__ b2,
            float* __restrict__ out)
{
    extern __shared__ float smem[];
    float* xs = smem;                                    // 3 x 64KB slabs (swizzled)
    float* wx = xs + 3 * (XSLAB_BYTES / 4);              // 3 x 40 (b1, w2, b2)
    int* sRow = (int*)(wx + 3 * 40);                     // 3 x 128

    int nT = g_numTiles;
    int q = (nT + GRID_MAIN - 1) / GRID_MAIN;
    int t0 = blockIdx.x * q;
    int t1 = t0 + q; if (t1 > nT) t1 = nT;
    int n = t1 - t0;
    if (n <= 0) return;

    int tid = threadIdx.x;
    int wid = tid >> 5;
    int t = tid & 31;
    uint32_t xs_sh = (uint32_t)__cvta_generic_to_shared(xs);
    uint32_t wx_sh = (uint32_t)__cvta_generic_to_shared(wx);

    auto tile_meta = [&](int tt, int& e, int& rs, int& v) {
        e = 0;
        #pragma unroll
        for (int j = 1; j < EE; j++)
            if (tt >= g_tileOff[j]) e = j;
        int ti = tt - g_tileOff[e];
        rs = g_offsets[e] + ti * M_TILE;
        v = g_offsets[e + 1] - rs;
        if (v > M_TILE) v = M_TILE;
    };
    auto stage_wx = [&](int e, int slot) {
        uint32_t dst = wx_sh + (uint32_t)slot * 160u;
        if (tid < 4)       cp_async16(dst + tid * 16u, b1 + e * HH + tid * 4);
        else if (tid < 8)  cp_async16(dst + 64u + (tid - 4) * 16u, W2 + e * HH + (tid - 4) * 4);
        else if (tid == 8) cp_async4(dst + 128u, b2 + e);
    };
    auto stage_x = [&](int slot, const int* rp) {
        uint32_t bb = xs_sh + (uint32_t)slot * XSLAB_BYTES;
        #pragma unroll
        for (int m = 0; m < 8; m++) {
            int idx = tid + m * THREADS;       // 4096 16B chunks
            int r = idx >> 5, s = idx & 31;
            int row = rp[r];
            uint32_t dst = bb + (uint32_t)(r * 512) + (uint32_t)(((s ^ (r & 7)) << 4));
            cp_async16(dst, x + (size_t)row * DD + s * 4);
        }
    };

    // ---- prologue: slabs 0 and 1 ----
    int eSlot0 = -1, eSlot1 = -1, eSlot2 = -1;
    {
        int e0, rs0, v0;
        tile_meta(t0, e0, rs0, v0);
        if (tid < M_TILE) sRow[tid] = g_perm[rs0 + ((tid < v0) ? tid : 0)];
        int e1 = -1;
        if (n > 1) {
            int rs1, v1;
            tile_meta(t0 + 1, e1, rs1, v1);
            if (tid < M_TILE) sRow[M_TILE + tid] = g_perm[rs1 + ((tid < v1) ? tid : 0)];
        }
        __syncthreads();
        stage_wx(e0, 0); eSlot0 = e0;
        stage_x(0, sRow);
        CP_COMMIT();
        if (n > 1) {
            stage_wx(e1, 1); eSlot1 = e1;
            stage_x(1, sRow + M_TILE);
        }
        CP_COMMIT();
    }

    // prefetch perm rows for slab 2
    int rr = 0;
    if (n > 2) {
        int e2, rs2, v2;
        tile_meta(t0 + 2, e2, rs2, v2);
        if (tid < M_TILE) rr = g_perm[rs2 + ((tid < v2) ? tid : 0)];
    }

    // constant per-thread addressing
    uint32_t xsw = (uint32_t)((t >> 2) << 2);                  // word-level xor (r&7 = t/4)
    uint32_t xrow0 = (uint32_t)((wid * 8 + (t >> 2)) * 512);   // this warp's 8 rows

    // register-resident W A-fragments (tf32 bit patterns), loaded from gmem
    uint32_t aw0[16], aw1[16], aw2[16], aw3[16];
    int eReg = -1;

    for (int j = 0; j < n; j++) {
        int slot  = j % 3;
        int slot2 = (j + 2) % 3;

        __syncthreads();                              // prior compute done; slot2 free
        if (j + 2 < n && tid < M_TILE) sRow[slot2 * M_TILE + tid] = rr;
        __syncthreads();

        if (j + 2 < n) {
            int e2, rs2, v2;
            tile_meta(t0 + j + 2, e2, rs2, v2);
            int eCur = (slot2 == 0) ? eSlot0 : (slot2 == 1) ? eSlot1 : eSlot2;
            if (e2 != eCur) {
                stage_wx(e2, slot2);
                if (slot2 == 0) eSlot0 = e2; else if (slot2 == 1) eSlot1 = e2; else eSlot2 = e2;
            }
            stage_x(slot2, sRow + slot2 * M_TILE);
        }
        CP_COMMIT();

        // prefetch perm rows for slab j+3 (overlaps the wait)
        if (j + 3 < n) {
            int e3, rs3, v3;
            tile_meta(t0 + j + 3, e3, rs3, v3);
            if (tid < M_TILE) rr = g_perm[rs3 + ((tid < v3) ? tid : 0)];
        }

        int ej, rsj, vj;
        tile_meta(t0 + j, ej, rsj, vj);

        // reload W A-frags from gmem on expert change (1-2x per CTA, L2-hot)
        if (ej != eReg) {
            eReg = ej;
            const float* Ws = g_Wsplit[ej];
            #pragma unroll
            for (int k = 0; k < 16; k++) {
                int base = (8 * k + (t & 3)) * HH + (t >> 2);
                aw0[k] = __float_as_uint(Ws[base]);         // [d][h]
                aw1[k] = __float_as_uint(Ws[base + 8]);     // h+8
                aw2[k] = __float_as_uint(Ws[base + 64]);    // d+4
                aw3[k] = __float_as_uint(Ws[base + 72]);    // h+8, d+4
            }
        }

        CP_WAIT2();
        __syncthreads();

        // ---- compute slab j: warp's 8 rows x 128 d -> 16 h, hi+lo chains ----
        uint32_t xb = xs_sh + (uint32_t)slot * XSLAB_BYTES + xrow0;
        float ch0 = 0.f, ch1 = 0.f, ch2 = 0.f, ch3 = 0.f;   // hi accum
        float cl0 = 0.f, cl1 = 0.f, cl2 = 0.f, cl3 = 0.f;   // lo accum

        #pragma unroll
        for (int k = 0; k < 16; k++) {
            uint32_t a00 = xb + (((uint32_t)(8 * k + (t & 3)) ^ xsw) << 2);
            float f00, f01;
            asm("ld.shared.f32 %0, [%1];" : "=f"(f00) : "r"(a00));
            asm("ld.shared.f32 %0, [%1];" : "=f"(f01) : "r"(a00 ^ 16u));
            uint32_t h00, h01;
            asm("cvt.rna.tf32.f32 %0, %1;" : "=r"(h00) : "f"(f00));
            asm("cvt.rna.tf32.f32 %0, %1;" : "=r"(h01) : "f"(f01));
            uint32_t l00 = __float_as_uint(f00 - __uint_as_float(h00));
            uint32_t l01 = __float_as_uint(f01 - __uint_as_float(h01));
            MMA_TF32(ch0, ch1, ch2, ch3, aw0[k], aw1[k], aw2[k], aw3[k], h00, h01);
            MMA_TF32(cl0, cl1, cl2, cl3, aw0[k], aw1[k], aw2[k], aw3[k], l00, l01);
        }

        // ---- epilogue: relu, dot w2, h-reduce via shfl, store ----
        {
            const float* wxp = wx + slot * 40;
            int h = t >> 2;
            float b1lo = wxp[h],      b1hi = wxp[h + 8];
            float w2lo = wxp[16 + h], w2hi = wxp[16 + h + 8];
            float b2v  = wxp[32];

            float pe = fmaxf(ch0 + cl0 + b1lo, 0.f) * w2lo
                     + fmaxf(ch2 + cl2 + b1hi, 0.f) * w2hi;
            float po = fmaxf(ch1 + cl1 + b1lo, 0.f) * w2lo
                     + fmaxf(ch3 + cl3 + b1hi, 0.f) * w2hi;
            #pragma unroll
            for (int d = 4; d < 32; d <<= 1) {
                pe += __shfl_xor_sync(0xFFFFFFFFu, pe, d);
                po += __shfl_xor_sync(0xFFFFFFFFu, po, d);
            }
            if (t < 4) {
                const int* rp = sRow + slot * M_TILE;
                int r0 = wid * 8 + 2 * t;
                if (r0 < vj)     out[rp[r0]]     = fmaxf(pe + b2v, 0.f);
                if (r0 + 1 < vj) out[rp[r0 + 1]] = fmaxf(po + b2v, 0.f);
            }
        }
    }
}

extern "C" void kernel_launch(void* const* d_in, const int* in_sizes, int n_in,
                              void* d_out, int out_size)
{
    const float* x   = (const float*)d_in[0];
    const int*   sid = (const int*)d_in[1];
    const float* W1  = (const float*)d_in[2];
    const float* b1  = (const float*)d_in[3];
    const float* W2  = (const float*)d_in[4];
    const float* b2  = (const float*)d_in[5];
    float* out = (float*)d_out;

    static bool attr_set = false;
    if (!attr_set) {
        cudaFuncSetAttribute(k_main, cudaFuncAttributeMaxDynamicSharedMemorySize, SMEM_BYTES);
        attr_set = true;
    }

    k_hist<<<NROWS / 4096, 1024>>>(sid);
    k_scan_prep<<<1 + EE, 128>>>(W1);
    k_scatter<<<NROWS / 1024, 1024>>>(sid);
    k_main<<<GRID_MAIN, THREADS, SMEM_BYTES>>>(x, W1, b1, W2, b2, out);
}

// round 11
// speedup vs baseline: 1.1238x; 1.1238x over previous
#include <cuda_runtime.h>
#include <cuda_bf16.h>
#include <cstdint>

#define NROWS 262144
#define DD 128
#define HH 16
#define EE 21

#define THREADS 512                // 16 warps
#define M_TILE 128                 // rows per slab (16 warps x 8 rows)
#define GRID_MAIN 148

#define XROW_BYTES 528             // 512 data + 16 pad: bank = (4r + d) % 32, conflict-free
#define XSLAB_BYTES (M_TILE * XROW_BYTES)     // 67584
#define SMEM_BYTES (3 * XSLAB_BYTES + 3 * M_TILE * 4 + 64)

__device__ int g_counts[EE];
__device__ int g_cursor[EE];
__device__ int g_offsets[EE + 1];
__device__ int g_tileOff[EE + 1];
__device__ int g_numTiles;
__device__ int g_perm[NROWS];
__device__ float g_Wsplit[EE][DD * HH];   // tf32-rounded W1, [d][h] contiguous

// ---------------- K1: histogram (int4 vectorized) ----------------
__global__ void k_hist(const int* __restrict__ sid) {
    __shared__ int sh[EE];
    int tid = threadIdx.x;
    if (tid < EE) sh[tid] = 0;
    __syncthreads();
    int4 v = ((const int4*)sid)[blockIdx.x * blockDim.x + tid];
    atomicAdd(&sh[v.x], 1);
    atomicAdd(&sh[v.y], 1);
    atomicAdd(&sh[v.z], 1);
    atomicAdd(&sh[v.w], 1);
    __syncthreads();
    if (tid < EE) atomicAdd(&g_counts[tid], sh[tid]);
}

// ---------------- K2: block0 = warp scan; blocks 1..21 = tf32 weight prep ----
__global__ void k_scan_prep(const float* __restrict__ W1) {
    if (blockIdx.x == 0) {
        if (threadIdx.x < 32) {
            int t = threadIdx.x;
            int c  = (t < EE) ? g_counts[t] : 0;
            int tl = (c + M_TILE - 1) / M_TILE;
            int ic = c, it = tl;
            #pragma unroll
            for (int d = 1; d < 32; d <<= 1) {
                int vc = __shfl_up_sync(0xFFFFFFFFu, ic, d);
                int vt = __shfl_up_sync(0xFFFFFFFFu, it, d);
                if (t >= d) { ic += vc; it += vt; }
            }
            if (t < EE) {
                g_offsets[t] = ic - c;
                g_cursor[t]  = ic - c;
                g_tileOff[t] = it - tl;
                g_counts[t]  = 0;
            }
            int totC = __shfl_sync(0xFFFFFFFFu, ic, EE - 1);
            int totT = __shfl_sync(0xFFFFFFFFu, it, EE - 1);
            if (t == 0) {
                g_offsets[EE] = totC;
                g_tileOff[EE] = totT;
                g_numTiles = totT;
            }
        }
    } else {
        int e = blockIdx.x - 1;
        for (int i = threadIdx.x; i < DD * HH; i += blockDim.x) {
            float w = W1[e * DD * HH + i];
            uint32_t hb;
            asm("cvt.rna.tf32.f32 %0, %1;" : "=r"(hb) : "f"(w));
            g_Wsplit[e][i] = __uint_as_float(hb);
        }
    }
}

// ---------------- K3: scatter ----------------
__global__ void k_scatter(const int* __restrict__ sid) {
    __shared__ int sHist[EE];
    __shared__ int sBase[EE];
    int tid = threadIdx.x;
    if (tid < EE) sHist[tid] = 0;
    __syncthreads();
    int gid = blockIdx.x * blockDim.x + tid;
    int e = sid[gid];
    int myIdx = atomicAdd(&sHist[e], 1);
    __syncthreads();
    if (tid < EE) sBase[tid] = atomicAdd(&g_cursor[tid], sHist[tid]);
    __syncthreads();
    g_perm[sBase[e] + myIdx] = gid;
}

// ---------------- K4: bulk-copy + tf32-MMA persistent expert MLP ----------
#define MMA_TF32(C0,C1,C2,C3, A0,A1,A2,A3, B0,B1)                                  \
    asm volatile("mma.sync.aligned.m16n8k8.row.col.f32.tf32.tf32.f32 "             \
        "{%0,%1,%2,%3}, {%4,%5,%6,%7}, {%8,%9}, {%0,%1,%2,%3};"                    \
        : "+f"(C0), "+f"(C1), "+f"(C2), "+f"(C3)                                   \
        : "r"(A0), "r"(A1), "r"(A2), "r"(A3), "r"(B0), "r"(B1))

__device__ __forceinline__ void mbar_init(uint32_t mbar, uint32_t count) {
    asm volatile("mbarrier.init.shared.b64 [%0], %1;" :: "r"(mbar), "r"(count) : "memory");
}
__device__ __forceinline__ void mbar_expect_tx(uint32_t mbar, uint32_t bytes) {
    asm volatile("mbarrier.arrive.expect_tx.shared.b64 _, [%0], %1;"
                 :: "r"(mbar), "r"(bytes) : "memory");
}
__device__ __forceinline__ void mbar_wait(uint32_t mbar, uint32_t parity) {
    uint32_t done;
    asm volatile(
        "{\n\t.reg .pred p;\n\t"
        "mbarrier.try_wait.parity.acquire.cta.shared::cta.b64 p, [%1], %2;\n\t"
        "selp.b32 %0, 1, 0, p;\n\t}"
        : "=r"(done) : "r"(mbar), "r"(parity) : "memory");
    if (!done) {
        asm volatile(
            "{\n\t.reg .pred P1;\n\t"
            "WAIT_LOOP_%=:\n\t"
            "mbarrier.try_wait.parity.acquire.cta.shared::cta.b64 P1, [%0], %1, 0x989680;\n\t"
            "@P1 bra.uni WAIT_DONE_%=;\n\t"
            "bra.uni WAIT_LOOP_%=;\n\t"
            "WAIT_DONE_%=:\n\t}"
            :: "r"(mbar), "r"(parity) : "memory");
    }
}
__device__ __forceinline__ void bulk_cp512(uint32_t dst, const void* src, uint32_t mbar) {
    asm volatile(
        "cp.async.bulk.shared::cta.global.mbarrier::complete_tx::bytes [%0], [%1], 512, [%2];"
        :: "r"(dst), "l"(src), "r"(mbar) : "memory");
}

__global__ __launch_bounds__(THREADS, 1)
void k_main(const float* __restrict__ x,
            const float* __restrict__ W1,
            const float* __restrict__ b1,
            const float* __restrict__ W2,
            const float* __restrict__ b2,
            float* __restrict__ out)
{
    extern __shared__ float smem[];
    float* xs = smem;                                    // 3 x 66KB slabs, 528B rows
    int* sRow = (int*)(xs + 3 * (XSLAB_BYTES / 4));      // 3 x 128
    // mbarriers: 3 x 8B, 16B aligned
    uint32_t mb_sh = (uint32_t)__cvta_generic_to_shared(sRow + 3 * M_TILE);
    mb_sh = (mb_sh + 15u) & ~15u;

    int nT = g_numTiles;
    int q = (nT + GRID_MAIN - 1) / GRID_MAIN;
    int t0 = blockIdx.x * q;
    int t1 = t0 + q; if (t1 > nT) t1 = nT;
    int n = t1 - t0;
    if (n <= 0) return;

    int tid = threadIdx.x;
    int wid = tid >> 5;
    int t = tid & 31;
    uint32_t xs_sh = (uint32_t)__cvta_generic_to_shared(xs);

    auto tile_meta = [&](int tt, int& e, int& rs, int& v) {
        e = 0;
        #pragma unroll
        for (int j = 1; j < EE; j++)
            if (tt >= g_tileOff[j]) e = j;
        int ti = tt - g_tileOff[e];
        rs = g_offsets[e] + ti * M_TILE;
        v = g_offsets[e + 1] - rs;
        if (v > M_TILE) v = M_TILE;
    };
    // stage slab: 128 x 512B bulk copies + one expect_tx
    auto stage_x = [&](int slot, const int* rp) {
        uint32_t mbar = mb_sh + (uint32_t)slot * 8u;
        if (tid == 0) mbar_expect_tx(mbar, (uint32_t)(M_TILE * 512));
        if (tid < M_TILE) {
            const float* src = x + (size_t)rp[tid] * DD;
            uint32_t dst = xs_sh + (uint32_t)slot * XSLAB_BYTES + (uint32_t)tid * XROW_BYTES;
            bulk_cp512(dst, src, mbar);
        }
    };

    // ---- init mbarriers ----
    if (tid == 0) {
        mbar_init(mb_sh + 0u, 1);
        mbar_init(mb_sh + 8u, 1);
        mbar_init(mb_sh + 16u, 1);
    }
    asm volatile("fence.proxy.async.shared::cta;" ::: "memory");
    __syncthreads();

    // ---- prologue: slabs 0 and 1 ----
    {
        int e0, rs0, v0;
        tile_meta(t0, e0, rs0, v0);
        if (tid < M_TILE) sRow[tid] = g_perm[rs0 + ((tid < v0) ? tid : 0)];
        if (n > 1) {
            int e1, rs1, v1;
            tile_meta(t0 + 1, e1, rs1, v1);
            if (tid < M_TILE) sRow[M_TILE + tid] = g_perm[rs1 + ((tid < v1) ? tid : 0)];
        }
        __syncthreads();
        stage_x(0, sRow);
        if (n > 1) stage_x(1, sRow + M_TILE);
    }

    // prefetch perm rows for slab 2
    int rr = 0;
    if (n > 2) {
        int e2, rs2, v2;
        tile_meta(t0 + 2, e2, rs2, v2);
        if (tid < M_TILE) rr = g_perm[rs2 + ((tid < v2) ? tid : 0)];
    }

    // constant per-thread addressing: warp's 8 rows, 528B stride
    uint32_t xrow0 = (uint32_t)((wid * 8 + (t >> 2)) * XROW_BYTES);
    uint32_t xcol0 = (uint32_t)((t & 3) * 4);

    // register-resident W A-frags + epilogue scalars, reloaded on expert change
    uint32_t aw0[16], aw1[16], aw2[16], aw3[16];
    float b1lo = 0.f, b1hi = 0.f, w2lo = 0.f, w2hi = 0.f, b2v = 0.f;
    int eReg = -1;
    int h = t >> 2;

    for (int j = 0; j < n; j++) {
        int slot  = j % 3;
        int slot2 = (j + 2) % 3;
        uint32_t parity = (uint32_t)((j / 3) & 1);

        __syncthreads();                              // prior compute done; slot2 free
        if (j + 2 < n && tid < M_TILE) sRow[slot2 * M_TILE + tid] = rr;
        __syncthreads();

        if (j + 2 < n) stage_x(slot2, sRow + slot2 * M_TILE);

        // prefetch perm rows for slab j+3 (overlaps the wait)
        if (j + 3 < n) {
            int e3, rs3, v3;
            tile_meta(t0 + j + 3, e3, rs3, v3);
            if (tid < M_TILE) rr = g_perm[rs3 + ((tid < v3) ? tid : 0)];
        }

        int ej, rsj, vj;
        tile_meta(t0 + j, ej, rsj, vj);

        // reload W frags + epilogue scalars on expert change (rare, L2-hot)
        if (ej != eReg) {
            eReg = ej;
            const float* Ws = g_Wsplit[ej];
            #pragma unroll
            for (int k = 0; k < 16; k++) {
                int base = (8 * k + (t & 3)) * HH + h;
                aw0[k] = __float_as_uint(Ws[base]);         // [d][h]
                aw1[k] = __float_as_uint(Ws[base + 8]);     // h+8
                aw2[k] = __float_as_uint(Ws[base + 64]);    // d+4
                aw3[k] = __float_as_uint(Ws[base + 72]);    // h+8, d+4
            }
            b1lo = __ldg(b1 + ej * HH + h);
            b1hi = __ldg(b1 + ej * HH + h + 8);
            w2lo = __ldg(W2 + ej * HH + h);
            w2hi = __ldg(W2 + ej * HH + h + 8);
            b2v  = __ldg(b2 + ej);
        }

        mbar_wait(mb_sh + (uint32_t)slot * 8u, parity);

        // ---- compute slab j: warp's 8 rows x 128 d -> 16 h, hi+lo chains ----
        uint32_t xb = xs_sh + (uint32_t)slot * XSLAB_BYTES + xrow0 + xcol0;
        float ch0 = 0.f, ch1 = 0.f, ch2 = 0.f, ch3 = 0.f;   // hi accum
        float cl0 = 0.f, cl1 = 0.f, cl2 = 0.f, cl3 = 0.f;   // lo accum

        #pragma unroll
        for (int k = 0; k < 16; k++) {
            uint32_t a00 = xb + (uint32_t)(k * 32);   // d = 8k + t%4
            float f00, f01;
            asm("ld.shared.f32 %0, [%1];" : "=f"(f00) : "r"(a00));
            asm("ld.shared.f32 %0, [%1];" : "=f"(f01) : "r"(a00 + 16));  // d+4
            uint32_t h00, h01;
            asm("cvt.rna.tf32.f32 %0, %1;" : "=r"(h00) : "f"(f00));
            asm("cvt.rna.tf32.f32 %0, %1;" : "=r"(h01) : "f"(f01));
            uint32_t l00 = __float_as_uint(f00 - __uint_as_float(h00));
            uint32_t l01 = __float_as_uint(f01 - __uint_as_float(h01));
            MMA_TF32(ch0, ch1, ch2, ch3, aw0[k], aw1[k], aw2[k], aw3[k], h00, h01);
            MMA_TF32(cl0, cl1, cl2, cl3, aw0[k], aw1[k], aw2[k], aw3[k], l00, l01);
        }

        // ---- epilogue: relu, dot w2, h-reduce via shfl, store ----
        {
            float pe = fmaxf(ch0 + cl0 + b1lo, 0.f) * w2lo
                     + fmaxf(ch2 + cl2 + b1hi, 0.f) * w2hi;
            float po = fmaxf(ch1 + cl1 + b1lo, 0.f) * w2lo
                     + fmaxf(ch3 + cl3 + b1hi, 0.f) * w2hi;
            #pragma unroll
            for (int d = 4; d < 32; d <<= 1) {
                pe += __shfl_xor_sync(0xFFFFFFFFu, pe, d);
                po += __shfl_xor_sync(0xFFFFFFFFu, po, d);
            }
            if (t < 4) {
                const int* rp = sRow + slot * M_TILE;
                int r0 = wid * 8 + 2 * t;
                if (r0 < vj)     out[rp[r0]]     = fmaxf(pe + b2v, 0.f);
                if (r0 + 1 < vj) out[rp[r0 + 1]] = fmaxf(po + b2v, 0.f);
            }
        }
    }
}

extern "C" void kernel_launch(void* const* d_in, const int* in_sizes, int n_in,
                              void* d_out, int out_size)
{
    const float* x   = (const float*)d_in[0];
    const int*   sid = (const int*)d_in[1];
    const float* W1  = (const float*)d_in[2];
    const float* b1  = (const float*)d_in[3];
    const float* W2  = (const float*)d_in[4];
    const float* b2  = (const float*)d_in[5];
    float* out = (float*)d_out;

    static bool attr_set = false;
    if (!attr_set) {
        cudaFuncSetAttribute(k_main, cudaFuncAttributeMaxDynamicSharedMemorySize, SMEM_BYTES);
        attr_set = true;
    }

    k_hist<<<NROWS / 4096, 1024>>>(sid);
    k_scan_prep<<<1 + EE, 128>>>(W1);
    k_scatter<<<NROWS / 1024, 1024>>>(sid);
    k_main<<<GRID_MAIN, THREADS, SMEM_BYTES>>>(x, W1, b1, W2, b2, out);
}